// round 10
// baseline (speedup 1.0000x reference)
#include <cuda_runtime.h>
#include <cstdint>

#define T_STEPS 2048
#define BATCH   64
#define IN_DIM  128
#define HDIM    256
#define OUT_DIM 128
#define NTHR    512
#define NBLK    128           // 16 groups (4 batch rows) x 8 ranks (32 h-cols)
#define WOPAD   272

// smem layout (floats)
#define OFF_ACT   0                       // [2][384][4]  = 3072
#define OFF_WOUT  3072                    // [16][272]    = 4352
#define OFF_G     7424                    // [128][4]     = 512
#define OFF_BIAS  7936                    // 128
#define OFF_BOUT  8064                    // 16
#define SMEM_FLOATS 8080
#define SMEM_BYTES (SMEM_FLOATS * 4)      // 32320

// persistent state: transposed h, double-buffered per group
__device__ float g_hT[16][2][HDIM * 4];   // [grp][buf][col*4 + r]
struct Flag { unsigned v; unsigned pad[31]; };
__device__ Flag g_flags[NBLK];

__device__ __forceinline__ unsigned ld_acq(const unsigned* p) {
    unsigned v;
    asm volatile("ld.acquire.gpu.global.u32 %0, [%1];" : "=r"(v) : "l"(p) : "memory");
    return v;
}
__device__ __forceinline__ void st_rel(unsigned* p, unsigned v) {
    asm volatile("st.release.gpu.global.u32 [%0], %1;" :: "l"(p), "r"(v) : "memory");
}

__global__ void __launch_bounds__(NTHR, 1) lstm_split_kernel(
    const float* __restrict__ input,   // [T, B, IN]
    const float* __restrict__ W_ih,    // [4H, IN]
    const float* __restrict__ W_hh,    // [4H, H]
    const float* __restrict__ b_ih,    // [4H]
    const float* __restrict__ b_hh,    // [4H]
    const float* __restrict__ W_out,   // [OUT, H]
    const float* __restrict__ b_out,   // [OUT]
    float* __restrict__ out,
    int out_size)
{
    extern __shared__ float sm[];
    float* sAct  = sm + OFF_ACT;   // [buf][k][r]: k<128 x, k>=128 h
    float* sWo   = sm + OFF_WOUT;
    float* sG    = sm + OFF_G;     // gates [m][r]
    float* sBias = sm + OFF_BIAS;
    float* sBOut = sm + OFF_BOUT;

    const int tid  = threadIdx.x;
    const int bid  = blockIdx.x;
    const int grp  = bid >> 3;
    const int rank = bid & 7;
    const int rbase = grp * 4;
    const int cb    = rank * 32;

    const unsigned base = ld_acq(&g_flags[bid].v);   // flags uniform at start

    // ---- gate-GEMM mapping: m = gate-col (tid>>2), kq = split-K (tid&3) ----
    const int m   = tid >> 2;
    const int kq  = tid & 3;
    const int g_  = m >> 5;
    const int col = m & 31;
    const int grow = g_ * HDIM + cb + col;

    // ---- weights in registers: 32 x-weights + 64 h-weights per thread ----
    float wreg[96];
    {
        const float* src_ih = W_ih + (size_t)grow * IN_DIM + kq * 32;
        const float* src_hh = W_hh + (size_t)grow * HDIM + kq * 64;
        #pragma unroll
        for (int i = 0; i < 32; i++) wreg[i] = __ldg(src_ih + i);
        #pragma unroll
        for (int i = 0; i < 64; i++) wreg[32 + i] = __ldg(src_hh + i);
    }

    // ---- smem preload ----
    for (int i = tid; i < 16 * HDIM; i += NTHR) {
        int o = i >> 8, k = i & 255;
        sWo[o * WOPAD + k] = W_out[(rank * 16 + o) * HDIM + k];
    }
    if (tid < 128) {
        int gi = tid >> 5, ci = tid & 31;
        int gr = gi * HDIM + cb + ci;
        sBias[tid] = b_ih[gr] + b_hh[gr];
    }
    if (tid < 16) sBOut[tid] = b_out[rank * 16 + tid];

    // zero both act buffers (h_0 = 0), x_0 transposed into buf0
    for (int i = tid; i < 2 * 384 * 4; i += NTHR) sAct[i] = 0.0f;
    __syncthreads();
    if (tid < 128) {
        int r = tid >> 5, k5 = tid & 31;
        float4 v = *(const float4*)(input + ((size_t)rbase + r) * IN_DIM + k5 * 4);
        sAct[(k5 * 4 + 0) * 4 + r] = v.x;
        sAct[(k5 * 4 + 1) * 4 + r] = v.y;
        sAct[(k5 * 4 + 2) * 4 + r] = v.z;
        sAct[(k5 * 4 + 3) * 4 + r] = v.w;
    }
    __syncthreads();

    const size_t Y_TOTAL = (size_t)T_STEPS * BATCH * OUT_DIM;
    const bool write_tail = (out_size >= (int)(Y_TOTAL + 2 * BATCH * HDIM));

    float c_reg = 0.0f;   // cell state (r=tid>>5, c=tid&31), threads 0-127

    for (int t = 0; t < T_STEPS; t++) {
        const int buf = t & 1;
        float* A  = sAct + buf * 1536;
        float* An = sAct + (1 - buf) * 1536;

        // ---- phase 1: issue h_t fill loads (tid<256); latency hides under x-GEMM ----
        float4 hv;
        if (tid < 256 && t > 0)
            hv = __ldcg(((const float4*)g_hT[grp][buf]) + tid);

        // ---- phase 2: x-part GEMM (K=128, prefetched x, independent of h_t) ----
        unsigned long long acc01 = 0ULL, acc23 = 0ULL;
        {
            const ulonglong2* av = ((const ulonglong2*)A) + kq * 32;
            #pragma unroll
            for (int i = 0; i < 32; i++) {
                ulonglong2 p = av[i];
                unsigned wu = __float_as_uint(wreg[i]);
                unsigned long long wp;
                asm("mov.b64 %0, {%1, %1};" : "=l"(wp) : "r"(wu));
                asm("fma.rn.f32x2 %0, %1, %2, %0;" : "+l"(acc01) : "l"(wp), "l"(p.x));
                asm("fma.rn.f32x2 %0, %1, %2, %0;" : "+l"(acc23) : "l"(wp), "l"(p.y));
            }
        }

        // ---- phase 3: land the fill ----
        if (tid < 256 && t > 0)
            ((float4*)A)[128 + tid] = hv;
        __syncthreads();

        // ---- phase 4: h-part GEMM (K=256, critical path) ----
        {
            const ulonglong2* av = ((const ulonglong2*)A) + 128 + kq * 64;
            #pragma unroll
            for (int i = 0; i < 64; i++) {
                ulonglong2 p = av[i];
                unsigned wu = __float_as_uint(wreg[32 + i]);
                unsigned long long wp;
                asm("mov.b64 %0, {%1, %1};" : "=l"(wp) : "r"(wu));
                asm("fma.rn.f32x2 %0, %1, %2, %0;" : "+l"(acc01) : "l"(wp), "l"(p.x));
                asm("fma.rn.f32x2 %0, %1, %2, %0;" : "+l"(acc23) : "l"(wp), "l"(p.y));
            }
        }

        // ---- phase 5: split-K reduce via shfl (kq = lane bits 0-1) ----
        {
            unsigned u0, u1, u2, u3;
            asm("mov.b64 {%0, %1}, %2;" : "=r"(u0), "=r"(u1) : "l"(acc01));
            asm("mov.b64 {%0, %1}, %2;" : "=r"(u2), "=r"(u3) : "l"(acc23));
            float f0 = __uint_as_float(u0), f1 = __uint_as_float(u1);
            float f2 = __uint_as_float(u2), f3 = __uint_as_float(u3);
            f0 += __shfl_xor_sync(0xffffffffu, f0, 1);
            f1 += __shfl_xor_sync(0xffffffffu, f1, 1);
            f2 += __shfl_xor_sync(0xffffffffu, f2, 1);
            f3 += __shfl_xor_sync(0xffffffffu, f3, 1);
            f0 += __shfl_xor_sync(0xffffffffu, f0, 2);
            f1 += __shfl_xor_sync(0xffffffffu, f1, 2);
            f2 += __shfl_xor_sync(0xffffffffu, f2, 2);
            f3 += __shfl_xor_sync(0xffffffffu, f3, 2);
            if (kq == 0) {
                float b = sBias[m];
                *(float4*)(sG + m * 4) = make_float4(f0 + b, f1 + b, f2 + b, f3 + b);
            }
        }
        __syncthreads();

        const unsigned tgt = base + 1 + (unsigned)t;

        // ---- phase 6: cell+release (w0-3) | x-prefetch (w4-7) | y_{t-1} (w8-15) ----
        if (tid < 128) {
            const int r = tid >> 5, c = tid & 31;
            float gi = sG[(0 * 32 + c) * 4 + r];
            float gf = sG[(1 * 32 + c) * 4 + r];
            float gg = sG[(2 * 32 + c) * 4 + r];
            float go = sG[(3 * 32 + c) * 4 + r];
            float i_ = 1.0f / (1.0f + __expf(-gi));
            float f_ = 1.0f / (1.0f + __expf(-gf));
            float gv = tanhf(gg);
            float o_ = 1.0f / (1.0f + __expf(-go));
            float cn = f_ * c_reg + i_ * gv;
            float hn = o_ * tanhf(cn);
            c_reg = cn;

            __stcg(&g_hT[grp][1 - buf][(cb + c) * 4 + r], hn);

            if (t == T_STEPS - 1 && write_tail) {
                out[Y_TOTAL + (size_t)(rbase + r) * HDIM + cb + c] = hn;
                out[Y_TOTAL + BATCH * HDIM + (size_t)(rbase + r) * HDIM + cb + c] = cn;
            }
            asm volatile("bar.sync 1, 128;" ::: "memory");
            if (tid == 0) st_rel(&g_flags[bid].v, tgt);
        } else if (tid < 256) {
            if (t + 1 < T_STEPS) {
                int xr = (tid - 128) >> 5, xk5 = (tid - 128) & 31;
                float4 v = __ldcg((const float4*)(input
                        + ((size_t)(t + 1) * BATCH + rbase + xr) * IN_DIM + xk5 * 4));
                An[(xk5 * 4 + 0) * 4 + xr] = v.x;
                An[(xk5 * 4 + 1) * 4 + xr] = v.y;
                An[(xk5 * 4 + 2) * 4 + xr] = v.z;
                An[(xk5 * 4 + 3) * 4 + xr] = v.w;
            }
        } else if (t > 0) {
            const int slot = tid - 256;
            const int o = slot >> 4, ks = slot & 15;
            float y0 = 0.f, y1 = 0.f, y2 = 0.f, y3 = 0.f;
            const float* wo = sWo + o * WOPAD + ks;
            const float4* ah = ((const float4*)A) + 128 + ks;
            #pragma unroll
            for (int i = 0; i < 16; i++) {
                float w = wo[i * 16];
                float4 h4 = ah[i * 16];
                y0 += w * h4.x; y1 += w * h4.y; y2 += w * h4.z; y3 += w * h4.w;
            }
            #pragma unroll
            for (int s = 1; s <= 8; s <<= 1) {
                y0 += __shfl_xor_sync(0xffffffffu, y0, s);
                y1 += __shfl_xor_sync(0xffffffffu, y1, s);
                y2 += __shfl_xor_sync(0xffffffffu, y2, s);
                y3 += __shfl_xor_sync(0xffffffffu, y3, s);
            }
            if (ks == 0) {
                float b = sBOut[o];
                size_t yb = ((size_t)(t - 1) * BATCH + rbase) * OUT_DIM
                            + (size_t)rank * 16 + o;
                out[yb + 0 * OUT_DIM] = y0 + b;
                out[yb + 1 * OUT_DIM] = y1 + b;
                out[yb + 2 * OUT_DIM] = y2 + b;
                out[yb + 3 * OUT_DIM] = y3 + b;
            }
        }

        // ---- phase 7: poll (8 threads ONLY — proven safe poller count) ----
        if (tid < 8) {
            const unsigned* p = &g_flags[grp * 8 + tid].v;
            while (ld_acq(p) < tgt) { }
        }
        __syncthreads();
    }

    // ---- tail: y_{T-1} from h_T (g_hT[grp][0]; flags already at base+2048) ----
    {
        float* A = sAct;   // buf 0
        if (tid < 256) {
            float4 v = __ldcg(((const float4*)g_hT[grp][0]) + tid);
            ((float4*)A)[128 + tid] = v;
        }
        __syncthreads();
        if (tid >= 256) {
            const int slot = tid - 256;
            const int o = slot >> 4, ks = slot & 15;
            float y0 = 0.f, y1 = 0.f, y2 = 0.f, y3 = 0.f;
            const float* wo = sWo + o * WOPAD + ks;
            const float4* ah = ((const float4*)A) + 128 + ks;
            #pragma unroll
            for (int i = 0; i < 16; i++) {
                float w = wo[i * 16];
                float4 h4 = ah[i * 16];
                y0 += w * h4.x; y1 += w * h4.y; y2 += w * h4.z; y3 += w * h4.w;
            }
            #pragma unroll
            for (int s = 1; s <= 8; s <<= 1) {
                y0 += __shfl_xor_sync(0xffffffffu, y0, s);
                y1 += __shfl_xor_sync(0xffffffffu, y1, s);
                y2 += __shfl_xor_sync(0xffffffffu, y2, s);
                y3 += __shfl_xor_sync(0xffffffffu, y3, s);
            }
            if (ks == 0) {
                float b = sBOut[o];
                size_t yb = ((size_t)(T_STEPS - 1) * BATCH + rbase) * OUT_DIM
                            + (size_t)rank * 16 + o;
                out[yb + 0 * OUT_DIM] = y0 + b;
                out[yb + 1 * OUT_DIM] = y1 + b;
                out[yb + 2 * OUT_DIM] = y2 + b;
                out[yb + 3 * OUT_DIM] = y3 + b;
            }
        }
    }
}

extern "C" void kernel_launch(void* const* d_in, const int* in_sizes, int n_in,
                              void* d_out, int out_size) {
    const float* input = (const float*)d_in[0];
    const float* W_ih  = (const float*)d_in[1];
    const float* W_hh  = (const float*)d_in[2];
    const float* b_ih  = (const float*)d_in[3];
    const float* b_hh  = (const float*)d_in[4];
    const float* W_out = (const float*)d_in[5];
    const float* b_out = (const float*)d_in[6];
    float* out = (float*)d_out;
    (void)in_sizes; (void)n_in;

    cudaFuncSetAttribute(lstm_split_kernel,
                         cudaFuncAttributeMaxDynamicSharedMemorySize, SMEM_BYTES);
    lstm_split_kernel<<<NBLK, NTHR, SMEM_BYTES>>>(
        input, W_ih, W_hh, b_ih, b_hh, W_out, b_out, out, out_size);
}

// round 11
// speedup vs baseline: 4.1854x; 4.1854x over previous
#include <cuda_runtime.h>
#include <cstdint>

#define T_STEPS 2048
#define BATCH   64
#define IN_DIM  128
#define HDIM    256
#define OUT_DIM 128
#define NTHR    512
#define NBLK    128           // 16 groups (4 batch rows) x 8 ranks (32 h-cols)
#define WOPAD   272

// smem layout (floats)
#define OFF_ACT   0                       // [2][384][4]  = 3072
#define OFF_WOUT  3072                    // [16][272]    = 4352
#define OFF_P     7424                    // [4][128][4]  = 2048
#define OFF_G     9472                    // [128][4]     = 512
#define OFF_BIAS  9984                    // 128
#define OFF_BOUT  10112                   // 16
#define SMEM_FLOATS 10128
#define SMEM_BYTES (SMEM_FLOATS * 4)      // 40512

// persistent state: transposed h, double-buffered per group
__device__ float g_hT[16][2][HDIM * 4];   // [grp][buf][col*4 + r]
struct Flag { unsigned v; unsigned pad[31]; };
__device__ Flag g_flags[NBLK];

__device__ __forceinline__ unsigned ld_acq(const unsigned* p) {
    unsigned v;
    asm volatile("ld.acquire.gpu.global.u32 %0, [%1];" : "=r"(v) : "l"(p) : "memory");
    return v;
}
__device__ __forceinline__ void st_rel(unsigned* p, unsigned v) {
    asm volatile("st.release.gpu.global.u32 [%0], %1;" :: "l"(p), "r"(v) : "memory");
}

__global__ void __launch_bounds__(NTHR, 1) lstm_split2_kernel(
    const float* __restrict__ input,   // [T, B, IN]
    const float* __restrict__ W_ih,    // [4H, IN]
    const float* __restrict__ W_hh,    // [4H, H]
    const float* __restrict__ b_ih,    // [4H]
    const float* __restrict__ b_hh,    // [4H]
    const float* __restrict__ W_out,   // [OUT, H]
    const float* __restrict__ b_out,   // [4H]
    float* __restrict__ out,
    int out_size)
{
    extern __shared__ float sm[];
    float* sAct  = sm + OFF_ACT;   // [buf][k][r]: k<128 x, k>=128 h
    float* sWo   = sm + OFF_WOUT;
    float* sP    = sm + OFF_P;     // split-K partials
    float* sG    = sm + OFF_G;     // reduced gates [m][r]
    float* sBias = sm + OFF_BIAS;
    float* sBOut = sm + OFF_BOUT;

    const int tid  = threadIdx.x;
    const int bid  = blockIdx.x;
    const int grp  = bid >> 3;
    const int rank = bid & 7;
    const int rbase = grp * 4;
    const int cb    = rank * 32;

    const unsigned base = ld_acq(&g_flags[bid].v);   // flags uniform at start

    // ---- gate-GEMM mapping (R7): m = tid&127, kq = tid>>7 (warp-uniform!) ----
    // kq warp-uniform => all activation LDS are broadcasts (conflict-free).
    const int m   = tid & 127;
    const int kq  = tid >> 7;
    const int g_  = m >> 5;
    const int col = m & 31;
    const int grow = g_ * HDIM + cb + col;

    // ---- weights in registers: 32 x-weights + 64 h-weights per thread ----
    float wreg[96];
    {
        const float* src_ih = W_ih + (size_t)grow * IN_DIM + kq * 32;
        const float* src_hh = W_hh + (size_t)grow * HDIM + kq * 64;
        #pragma unroll
        for (int i = 0; i < 32; i++) wreg[i] = __ldg(src_ih + i);
        #pragma unroll
        for (int i = 0; i < 64; i++) wreg[32 + i] = __ldg(src_hh + i);
    }

    // ---- smem preload ----
    for (int i = tid; i < 16 * HDIM; i += NTHR) {
        int o = i >> 8, k = i & 255;
        sWo[o * WOPAD + k] = W_out[(rank * 16 + o) * HDIM + k];
    }
    if (tid < 128) sBias[tid] = b_ih[grow] + b_hh[grow];   // tid<128 -> m==tid
    if (tid < 16) sBOut[tid] = b_out[rank * 16 + tid];

    // zero both act buffers (h_0 = 0), x_0 transposed into buf0
    for (int i = tid; i < 2 * 384 * 4; i += NTHR) sAct[i] = 0.0f;
    __syncthreads();
    if (tid < 128) {
        int r = tid >> 5, k5 = tid & 31;
        float4 v = *(const float4*)(input + ((size_t)rbase + r) * IN_DIM + k5 * 4);
        sAct[(k5 * 4 + 0) * 4 + r] = v.x;
        sAct[(k5 * 4 + 1) * 4 + r] = v.y;
        sAct[(k5 * 4 + 2) * 4 + r] = v.z;
        sAct[(k5 * 4 + 3) * 4 + r] = v.w;
    }
    __syncthreads();

    const size_t Y_TOTAL = (size_t)T_STEPS * BATCH * OUT_DIM;
    const bool write_tail = (out_size >= (int)(Y_TOTAL + 2 * BATCH * HDIM));

    float c_reg = 0.0f;   // cell state (r=tid>>5, c=tid&31), threads 0-127

    for (int t = 0; t < T_STEPS; t++) {
        const int buf = t & 1;
        float* A  = sAct + buf * 1536;
        float* An = sAct + (1 - buf) * 1536;

        // ---- phase 1: issue h_t fill LDGs (visibility guaranteed by poll
        //      of step t-1); latency hides under the x-part GEMM ----
        float4 hv;
        if (tid < 256 && t > 0)
            hv = __ldcg(((const float4*)g_hT[grp][buf]) + tid);

        // ---- phase 2: x-part GEMM (K=128; x prefetched last step) ----
        unsigned long long acc01 = 0ULL, acc23 = 0ULL;
        {
            const ulonglong2* av = ((const ulonglong2*)A) + kq * 32;
            #pragma unroll
            for (int i = 0; i < 32; i++) {
                ulonglong2 p = av[i];
                unsigned wu = __float_as_uint(wreg[i]);
                unsigned long long wp;
                asm("mov.b64 %0, {%1, %1};" : "=l"(wp) : "r"(wu));
                asm("fma.rn.f32x2 %0, %1, %2, %0;" : "+l"(acc01) : "l"(wp), "l"(p.x));
                asm("fma.rn.f32x2 %0, %1, %2, %0;" : "+l"(acc23) : "l"(wp), "l"(p.y));
            }
        }

        // ---- phase 3: land the fill ----
        if (tid < 256 && t > 0)
            ((float4*)A)[128 + tid] = hv;
        __syncthreads();

        // ---- phase 4: h-part GEMM (K=256; critical path) ----
        {
            const ulonglong2* av = ((const ulonglong2*)A) + 128 + kq * 64;
            #pragma unroll
            for (int i = 0; i < 64; i++) {
                ulonglong2 p = av[i];
                unsigned wu = __float_as_uint(wreg[32 + i]);
                unsigned long long wp;
                asm("mov.b64 %0, {%1, %1};" : "=l"(wp) : "r"(wu));
                asm("fma.rn.f32x2 %0, %1, %2, %0;" : "+l"(acc01) : "l"(wp), "l"(p.x));
                asm("fma.rn.f32x2 %0, %1, %2, %0;" : "+l"(acc23) : "l"(wp), "l"(p.y));
            }
            unsigned u0, u1, u2, u3;
            asm("mov.b64 {%0, %1}, %2;" : "=r"(u0), "=r"(u1) : "l"(acc01));
            asm("mov.b64 {%0, %1}, %2;" : "=r"(u2), "=r"(u3) : "l"(acc23));
            *(float4*)(sP + (kq * 128 + m) * 4) =
                make_float4(__uint_as_float(u0), __uint_as_float(u1),
                            __uint_as_float(u2), __uint_as_float(u3));
        }
        __syncthreads();

        const unsigned tgt = base + 1 + (unsigned)t;

        // ---- phase 5: reduce+cell+release (w0-3) | x-prefetch (w4-7) | y (w8-15) ----
        if (tid < 128) {
            const float4* p4 = (const float4*)sP;
            float4 s0 = p4[tid], s1 = p4[128 + tid], s2 = p4[256 + tid], s3 = p4[384 + tid];
            float b = sBias[tid];
            *(float4*)(sG + tid * 4) = make_float4(
                s0.x + s1.x + s2.x + s3.x + b,
                s0.y + s1.y + s2.y + s3.y + b,
                s0.z + s1.z + s2.z + s3.z + b,
                s0.w + s1.w + s2.w + s3.w + b);
            asm volatile("bar.sync 1, 128;" ::: "memory");

            const int r = tid >> 5, c = tid & 31;
            float gi = sG[(0 * 32 + c) * 4 + r];
            float gf = sG[(1 * 32 + c) * 4 + r];
            float gg = sG[(2 * 32 + c) * 4 + r];
            float go = sG[(3 * 32 + c) * 4 + r];
            float i_ = 1.0f / (1.0f + __expf(-gi));
            float f_ = 1.0f / (1.0f + __expf(-gf));
            float gv = tanhf(gg);
            float o_ = 1.0f / (1.0f + __expf(-go));
            float cn = f_ * c_reg + i_ * gv;
            float hn = o_ * tanhf(cn);
            c_reg = cn;

            __stcg(&g_hT[grp][1 - buf][(cb + c) * 4 + r], hn);

            if (t == T_STEPS - 1 && write_tail) {
                out[Y_TOTAL + (size_t)(rbase + r) * HDIM + cb + c] = hn;
                out[Y_TOTAL + BATCH * HDIM + (size_t)(rbase + r) * HDIM + cb + c] = cn;
            }
            asm volatile("bar.sync 1, 128;" ::: "memory");
            if (tid == 0) st_rel(&g_flags[bid].v, tgt);
        } else if (tid < 256) {
            if (t + 1 < T_STEPS) {
                int xr = (tid - 128) >> 5, xk5 = (tid - 128) & 31;
                float4 v = __ldcg((const float4*)(input
                        + ((size_t)(t + 1) * BATCH + rbase + xr) * IN_DIM + xk5 * 4));
                An[(xk5 * 4 + 0) * 4 + xr] = v.x;
                An[(xk5 * 4 + 1) * 4 + xr] = v.y;
                An[(xk5 * 4 + 2) * 4 + xr] = v.z;
                An[(xk5 * 4 + 3) * 4 + xr] = v.w;
            }
        } else if (t > 0) {
            const int slot = tid - 256;
            const int o = slot >> 4, ks = slot & 15;
            float y0 = 0.f, y1 = 0.f, y2 = 0.f, y3 = 0.f;
            const float* wo = sWo + o * WOPAD + ks;
            const float4* ah = ((const float4*)A) + 128 + ks;
            #pragma unroll
            for (int i = 0; i < 16; i++) {
                float w = wo[i * 16];
                float4 h4 = ah[i * 16];
                y0 += w * h4.x; y1 += w * h4.y; y2 += w * h4.z; y3 += w * h4.w;
            }
            #pragma unroll
            for (int s = 1; s <= 8; s <<= 1) {
                y0 += __shfl_xor_sync(0xffffffffu, y0, s);
                y1 += __shfl_xor_sync(0xffffffffu, y1, s);
                y2 += __shfl_xor_sync(0xffffffffu, y2, s);
                y3 += __shfl_xor_sync(0xffffffffu, y3, s);
            }
            if (ks == 0) {
                float b = sBOut[o];
                size_t yb = ((size_t)(t - 1) * BATCH + rbase) * OUT_DIM
                            + (size_t)rank * 16 + o;
                out[yb + 0 * OUT_DIM] = y0 + b;
                out[yb + 1 * OUT_DIM] = y1 + b;
                out[yb + 2 * OUT_DIM] = y2 + b;
                out[yb + 3 * OUT_DIM] = y3 + b;
            }
        }

        // ---- phase 6: poll (8 threads ONLY) ----
        if (tid < 8) {
            const unsigned* p = &g_flags[grp * 8 + tid].v;
            while (ld_acq(p) < tgt) { }
        }
        __syncthreads();
    }

    // ---- tail: y_{T-1} from h_T (g_hT[grp][0]; flags already at base+2048) ----
    {
        float* A = sAct;   // buf 0
        if (tid < 256) {
            float4 v = __ldcg(((const float4*)g_hT[grp][0]) + tid);
            ((float4*)A)[128 + tid] = v;
        }
        __syncthreads();
        if (tid >= 256) {
            const int slot = tid - 256;
            const int o = slot >> 4, ks = slot & 15;
            float y0 = 0.f, y1 = 0.f, y2 = 0.f, y3 = 0.f;
            const float* wo = sWo + o * WOPAD + ks;
            const float4* ah = ((const float4*)A) + 128 + ks;
            #pragma unroll
            for (int i = 0; i < 16; i++) {
                float w = wo[i * 16];
                float4 h4 = ah[i * 16];
                y0 += w * h4.x; y1 += w * h4.y; y2 += w * h4.z; y3 += w * h4.w;
            }
            #pragma unroll
            for (int s = 1; s <= 8; s <<= 1) {
                y0 += __shfl_xor_sync(0xffffffffu, y0, s);
                y1 += __shfl_xor_sync(0xffffffffu, y1, s);
                y2 += __shfl_xor_sync(0xffffffffu, y2, s);
                y3 += __shfl_xor_sync(0xffffffffu, y3, s);
            }
            if (ks == 0) {
                float b = sBOut[o];
                size_t yb = ((size_t)(T_STEPS - 1) * BATCH + rbase) * OUT_DIM
                            + (size_t)rank * 16 + o;
                out[yb + 0 * OUT_DIM] = y0 + b;
                out[yb + 1 * OUT_DIM] = y1 + b;
                out[yb + 2 * OUT_DIM] = y2 + b;
                out[yb + 3 * OUT_DIM] = y3 + b;
            }
        }
    }
}

extern "C" void kernel_launch(void* const* d_in, const int* in_sizes, int n_in,
                              void* d_out, int out_size) {
    const float* input = (const float*)d_in[0];
    const float* W_ih  = (const float*)d_in[1];
    const float* W_hh  = (const float*)d_in[2];
    const float* b_ih  = (const float*)d_in[3];
    const float* b_hh  = (const float*)d_in[4];
    const float* W_out = (const float*)d_in[5];
    const float* b_out = (const float*)d_in[6];
    float* out = (float*)d_out;
    (void)in_sizes; (void)n_in;

    cudaFuncSetAttribute(lstm_split2_kernel,
                         cudaFuncAttributeMaxDynamicSharedMemorySize, SMEM_BYTES);
    lstm_split2_kernel<<<NBLK, NTHR, SMEM_BYTES>>>(
        input, W_ih, W_hh, b_ih, b_hh, W_out, b_out, out, out_size);
}